// round 8
// baseline (speedup 1.0000x reference)
#include <cuda_runtime.h>
#include <math.h>

#define NN 50000
#define EE 800000

// Precomputed per-node tables (gathered per edge at dst; L2-resident)
__device__ __align__(16) float g_La[NN * 32];   // [n][c]
__device__ __align__(16) float g_Lv[NN * 96];   // [n][i][c], i in {x,y,z}, 32 channels each

// ---- shared memory layout (floats) for the edge kernel ----
#define OFF_C    0        // folded radial cos weights  [c][m] 32x16
#define OFF_S    512      // folded radial sin weights  [c][m] 32x16
#define OFF_W000 1024     // W_Y000^T [c][j] 32x64
#define OFF_W110 3072     // W_Y110^T [c][j] 32x64
#define OFF_W011 5120     // W_Y011^T [c][v] 32x16
#define OFF_W101 5632     // W_Y101^T [c][v] 32x16
#define OFF_W111 6144     // W_Y111^T [c][v] 32x16
#define OFF_M1   6656     // W_m1 [j][k] 64x64
#define OFF_M2   10752    // W_m2
#define OFF_M3   14848    // W_m3
#define OFF_BENC 18944    // 32
#define OFF_B1   18976    // 64
#define OFF_B2   19040    // 64
#define SMEM_FLOATS 19104
#define SMEM_BYTES  (SMEM_FLOATS * 4)

// ============================================================================
// Kernel A: per-node linear maps  La[n][c], Lv[n][i][c]
// ============================================================================
__global__ __launch_bounds__(128) void node_kernel(
    const float* __restrict__ x_a, const float* __restrict__ x_v,
    const float* __restrict__ W_L0, const float* __restrict__ W_L1)
{
    __shared__ float sW0[64 * 32];  // transposed [d][c] -> conflict-free
    __shared__ float sW1[16 * 32];
    int tid = threadIdx.x;
    for (int i = tid; i < 2048; i += 128) { int c = i >> 6, d = i & 63; sW0[d * 32 + c] = W_L0[i]; }
    for (int i = tid; i < 512;  i += 128) { int c = i >> 4, d = i & 15; sW1[d * 32 + c] = W_L1[i]; }
    __syncthreads();

    int n = blockIdx.x * 4 + (tid >> 5);
    int c = tid & 31;
    if (n >= NN) return;

    const float* xa = x_a + (size_t)n * 64;
    float acc = 0.f;
#pragma unroll
    for (int d = 0; d < 64; d++) acc = fmaf(__ldg(xa + d), sW0[d * 32 + c], acc);
    g_La[(size_t)n * 32 + c] = acc;

    const float* xv = x_v + (size_t)n * 48;  // [d][i]
    float ax = 0.f, ay = 0.f, az = 0.f;
#pragma unroll
    for (int d = 0; d < 16; d++) {
        float w = sW1[d * 32 + c];
        ax = fmaf(w, __ldg(xv + d * 3 + 0), ax);
        ay = fmaf(w, __ldg(xv + d * 3 + 1), ay);
        az = fmaf(w, __ldg(xv + d * 3 + 2), az);
    }
    g_Lv[(size_t)n * 96 +  0 + c] = ax;
    g_Lv[(size_t)n * 96 + 32 + c] = ay;
    g_Lv[(size_t)n * 96 + 64 + c] = az;
}

// ============================================================================
// 64x64 GEMV layer from smem weights (row-major [j][k]), fully unrolled.
// act: leaky_relu(0.1). accum: h += result (residual out-layer) else h = result.
// ============================================================================
__device__ __forceinline__ void layer64(const float* __restrict__ sw,
                                        const float* __restrict__ sb,
                                        const float (&x)[64], float (&h)[64],
                                        bool act, bool accum)
{
#pragma unroll
    for (int j4 = 0; j4 < 16; j4++) {
        float a0 = sb ? sb[j4 * 4 + 0] : 0.f;
        float a1 = sb ? sb[j4 * 4 + 1] : 0.f;
        float a2 = sb ? sb[j4 * 4 + 2] : 0.f;
        float a3 = sb ? sb[j4 * 4 + 3] : 0.f;
        const float4* w0 = (const float4*)(sw + (j4 * 4 + 0) * 64);
        const float4* w1 = (const float4*)(sw + (j4 * 4 + 1) * 64);
        const float4* w2 = (const float4*)(sw + (j4 * 4 + 2) * 64);
        const float4* w3 = (const float4*)(sw + (j4 * 4 + 3) * 64);
#pragma unroll
        for (int k4 = 0; k4 < 16; k4++) {
            float x0 = x[k4 * 4 + 0], x1 = x[k4 * 4 + 1];
            float x2 = x[k4 * 4 + 2], x3 = x[k4 * 4 + 3];
            float4 q;
            q = w0[k4]; a0 = fmaf(q.x, x0, fmaf(q.y, x1, fmaf(q.z, x2, fmaf(q.w, x3, a0))));
            q = w1[k4]; a1 = fmaf(q.x, x0, fmaf(q.y, x1, fmaf(q.z, x2, fmaf(q.w, x3, a1))));
            q = w2[k4]; a2 = fmaf(q.x, x0, fmaf(q.y, x1, fmaf(q.z, x2, fmaf(q.w, x3, a2))));
            q = w3[k4]; a3 = fmaf(q.x, x0, fmaf(q.y, x1, fmaf(q.z, x2, fmaf(q.w, x3, a3))));
        }
        if (act) {
            a0 = fmaxf(a0, 0.1f * a0); a1 = fmaxf(a1, 0.1f * a1);
            a2 = fmaxf(a2, 0.1f * a2); a3 = fmaxf(a3, 0.1f * a3);
        }
        if (accum) {
            h[j4 * 4 + 0] += a0; h[j4 * 4 + 1] += a1;
            h[j4 * 4 + 2] += a2; h[j4 * 4 + 3] += a3;
        } else {
            h[j4 * 4 + 0] = a0; h[j4 * 4 + 1] = a1;
            h[j4 * 4 + 2] = a2; h[j4 * 4 + 3] = a3;
        }
    }
}

// ============================================================================
// Kernel C: fused per-edge message kernel (1 thread = 1 edge)
// ============================================================================
__global__ __launch_bounds__(128) void edge_kernel(
    const float* __restrict__ r_ij, const int* __restrict__ src, const int* __restrict__ dst,
    const float* __restrict__ W_enc, const float* __restrict__ b_enc,
    const float* __restrict__ W_Y000, const float* __restrict__ W_Y110,
    const float* __restrict__ W_Y011, const float* __restrict__ W_Y101,
    const float* __restrict__ W_Y111,
    const float* __restrict__ W_m1, const float* __restrict__ b_m1,
    const float* __restrict__ W_m2, const float* __restrict__ b_m2,
    const float* __restrict__ W_m3, float* __restrict__ out)
{
    extern __shared__ float sm[];
    const int tid = threadIdx.x;

    // ---- stage weights (transposed / folded) into smem ----
    for (int i = tid; i < 512; i += 128) {        // folded radial: 16 distinct coeffs
        int c = i >> 4, m = i & 15;
        sm[OFF_C + i] = W_enc[c * 64 + 2 * m] + W_enc[c * 64 + 2 * m + 1];
        sm[OFF_S + i] = W_enc[c * 64 + 32 + 2 * m] + W_enc[c * 64 + 32 + 2 * m + 1];
    }
    for (int i = tid; i < 2048; i += 128) {       // [c][j] transposes
        int c = i >> 6, j = i & 63;
        sm[OFF_W000 + i] = W_Y000[j * 32 + c];
        sm[OFF_W110 + i] = W_Y110[j * 32 + c];
    }
    for (int i = tid; i < 512; i += 128) {        // [c][v] transposes
        int c = i >> 4, v = i & 15;
        sm[OFF_W011 + i] = W_Y011[v * 32 + c];
        sm[OFF_W101 + i] = W_Y101[v * 32 + c];
        sm[OFF_W111 + i] = W_Y111[v * 32 + c];
    }
    for (int i = tid; i < 4096; i += 128) {
        sm[OFF_M1 + i] = W_m1[i];
        sm[OFF_M2 + i] = W_m2[i];
        sm[OFF_M3 + i] = W_m3[i];
    }
    if (tid < 32) sm[OFF_BENC + tid] = b_enc[tid];
    if (tid < 64) { sm[OFF_B1 + tid] = b_m1[tid]; sm[OFF_B2 + tid] = b_m2[tid]; }
    __syncthreads();

    int e = blockIdx.x * 128 + tid;
    if (e >= EE) return;

    float rx = r_ij[(size_t)e * 3 + 0];
    float ry = r_ij[(size_t)e * 3 + 1];
    float rz = r_ij[(size_t)e * 3 + 2];
    int s = src[e], d = dst[e];

    float dist = sqrtf(rx * rx + ry * ry + rz * rz);

    // ---- radial features via Chebyshev recurrence (coeff multipliers 1..16) ----
    float u = 0.6283185307179586f * dist;   // pi/5
    float c1, s1;
    sincosf(u, &s1, &c1);
    float cosv[16], sinv[16];
    cosv[0] = c1; sinv[0] = s1;
    {
        float cp = 1.f, sp = 0.f, t2 = 2.f * c1;
#pragma unroll
        for (int m = 1; m < 16; m++) {
            float cn = fmaf(t2, cosv[m - 1], -cp);
            float sn = fmaf(t2, sinv[m - 1], -sp);
            cp = cosv[m - 1]; sp = sinv[m - 1];
            cosv[m] = cn; sinv[m] = sn;
        }
    }

    // ---- phi_a[c] = b_enc + folded radial dot ----
    float phi[32];
    const float4* sC4 = (const float4*)(sm + OFF_C);
    const float4* sS4 = (const float4*)(sm + OFF_S);
#pragma unroll
    for (int c = 0; c < 32; c++) {
        float acc = sm[OFF_BENC + c];
#pragma unroll
        for (int m4 = 0; m4 < 4; m4++) {
            float4 wc = sC4[c * 4 + m4];
            float4 ws = sS4[c * 4 + m4];
            acc = fmaf(wc.x, cosv[m4 * 4 + 0], acc);
            acc = fmaf(wc.y, cosv[m4 * 4 + 1], acc);
            acc = fmaf(wc.z, cosv[m4 * 4 + 2], acc);
            acc = fmaf(wc.w, cosv[m4 * 4 + 3], acc);
            acc = fmaf(ws.x, sinv[m4 * 4 + 0], acc);
            acc = fmaf(ws.y, sinv[m4 * 4 + 1], acc);
            acc = fmaf(ws.z, sinv[m4 * 4 + 2], acc);
            acc = fmaf(ws.w, sinv[m4 * 4 + 3], acc);
        }
        phi[c] = acc;
    }

    // ---- squashed edge vector rh (matches tens_sigmoid1(r*1.4)) ----
    float nrm = 1.4f * dist;
    float scl = 1.4f * tanhf(nrm) / fmaxf(nrm, 1e-12f);
    float rh0 = rx * scl, rh1 = ry * scl, rh2 = rz * scl;

    // ---- accumulators ----
    float psiA[64];
#pragma unroll
    for (int j = 0; j < 64; j++) psiA[j] = 0.f;
    float pvx[16], pvy[16], pvz[16], a011[16];
#pragma unroll
    for (int v = 0; v < 16; v++) { pvx[v] = 0.f; pvy[v] = 0.f; pvz[v] = 0.f; a011[v] = 0.f; }

    const float4* La4 = (const float4*)(g_La + (size_t)d * 32);
    const float4* Lv4 = (const float4*)(g_Lv + (size_t)d * 96);

#pragma unroll
    for (int q = 0; q < 8; q++) {
        float4 la4 = La4[q];
        float4 lx4 = Lv4[q], ly4 = Lv4[8 + q], lz4 = Lv4[16 + q];
        float laA[4] = {la4.x, la4.y, la4.z, la4.w};
        float lxA[4] = {lx4.x, lx4.y, lx4.z, lx4.w};
        float lyA[4] = {ly4.x, ly4.y, ly4.z, ly4.w};
        float lzA[4] = {lz4.x, lz4.y, lz4.z, lz4.w};
#pragma unroll
        for (int k = 0; k < 4; k++) {
            const int c = q * 4 + k;
            const float p = phi[c];
            const float lx = lxA[k], ly = lyA[k], lz = lzA[k];
            const float y000 = laA[k] * p;
            const float y110 = p * fmaf(lx, rh0, fmaf(ly, rh1, lz * rh2));
            const float plx = p * lx, ply = p * ly, plz = p * lz;
            // phi[c] * cross(l_v[c], rh)
            const float crx = fmaf(ply, rh2, -plz * rh1);
            const float cry = fmaf(plz, rh0, -plx * rh2);
            const float crz = fmaf(plx, rh1, -ply * rh0);

            // psi_a pre-projection
            const float4* w0 = (const float4*)(sm + OFF_W000 + c * 64);
            const float4* w1 = (const float4*)(sm + OFF_W110 + c * 64);
#pragma unroll
            for (int j4 = 0; j4 < 16; j4++) {
                float4 a = w0[j4], b = w1[j4];
                psiA[j4 * 4 + 0] = fmaf(a.x, y000, fmaf(b.x, y110, psiA[j4 * 4 + 0]));
                psiA[j4 * 4 + 1] = fmaf(a.y, y000, fmaf(b.y, y110, psiA[j4 * 4 + 1]));
                psiA[j4 * 4 + 2] = fmaf(a.z, y000, fmaf(b.z, y110, psiA[j4 * 4 + 2]));
                psiA[j4 * 4 + 3] = fmaf(a.w, y000, fmaf(b.w, y110, psiA[j4 * 4 + 3]));
            }
            // psi_v contractions
            const float4* wA = (const float4*)(sm + OFF_W011 + c * 16);
            const float4* wB = (const float4*)(sm + OFF_W101 + c * 16);
            const float4* wC = (const float4*)(sm + OFF_W111 + c * 16);
#pragma unroll
            for (int v4 = 0; v4 < 4; v4++) {
                float4 a = wA[v4], b = wB[v4], w = wC[v4];
                a011[v4 * 4 + 0] = fmaf(a.x, y000, a011[v4 * 4 + 0]);
                a011[v4 * 4 + 1] = fmaf(a.y, y000, a011[v4 * 4 + 1]);
                a011[v4 * 4 + 2] = fmaf(a.z, y000, a011[v4 * 4 + 2]);
                a011[v4 * 4 + 3] = fmaf(a.w, y000, a011[v4 * 4 + 3]);
                pvx[v4 * 4 + 0] = fmaf(b.x, plx, fmaf(w.x, crx, pvx[v4 * 4 + 0]));
                pvx[v4 * 4 + 1] = fmaf(b.y, plx, fmaf(w.y, crx, pvx[v4 * 4 + 1]));
                pvx[v4 * 4 + 2] = fmaf(b.z, plx, fmaf(w.z, crx, pvx[v4 * 4 + 2]));
                pvx[v4 * 4 + 3] = fmaf(b.w, plx, fmaf(w.w, crx, pvx[v4 * 4 + 3]));
                pvy[v4 * 4 + 0] = fmaf(b.x, ply, fmaf(w.x, cry, pvy[v4 * 4 + 0]));
                pvy[v4 * 4 + 1] = fmaf(b.y, ply, fmaf(w.y, cry, pvy[v4 * 4 + 1]));
                pvy[v4 * 4 + 2] = fmaf(b.z, ply, fmaf(w.z, cry, pvy[v4 * 4 + 2]));
                pvy[v4 * 4 + 3] = fmaf(b.w, ply, fmaf(w.w, cry, pvy[v4 * 4 + 3]));
                pvz[v4 * 4 + 0] = fmaf(b.x, plz, fmaf(w.x, crz, pvz[v4 * 4 + 0]));
                pvz[v4 * 4 + 1] = fmaf(b.y, plz, fmaf(w.y, crz, pvz[v4 * 4 + 1]));
                pvz[v4 * 4 + 2] = fmaf(b.z, plz, fmaf(w.z, crz, pvz[v4 * 4 + 2]));
                pvz[v4 * 4 + 3] = fmaf(b.w, plz, fmaf(w.w, crz, pvz[v4 * 4 + 3]));
            }
        }
    }

    // ---- scatter psi_v now (independent of MLP) to free registers ----
    {
        float* outV = out + (size_t)NN * 64 + (size_t)s * 48;
#pragma unroll
        for (int v = 0; v < 16; v++) {
            atomicAdd(outV + 3 * v + 0, 0.1f * fmaf(a011[v], rh0, pvx[v]));
            atomicAdd(outV + 3 * v + 1, 0.1f * fmaf(a011[v], rh1, pvy[v]));
            atomicAdd(outV + 3 * v + 2, 0.1f * fmaf(a011[v], rh2, pvz[v]));
        }
    }

    // ---- residual MLP on psi_a ----
    float h1[64], h2[64];
    layer64(sm + OFF_M1, sm + OFF_B1, psiA, h1, true, false);
    layer64(sm + OFF_M2, sm + OFF_B2, h1, h2, true, false);
    layer64(sm + OFF_M3, nullptr,    h2, psiA, false, true);   // psiA += W_m3 @ h2

    // ---- scatter psi_a ----
    {
        float* outA = out + (size_t)s * 64;
#pragma unroll
        for (int j = 0; j < 64; j++) atomicAdd(outA + j, 0.1f * psiA[j]);
    }
}

// ============================================================================
// launcher
// ============================================================================
extern "C" void kernel_launch(void* const* d_in, const int* in_sizes, int n_in,
                              void* d_out, int out_size)
{
    const float* r_ij   = (const float*)d_in[0];
    const float* x_a    = (const float*)d_in[1];
    const float* x_v    = (const float*)d_in[2];
    const int*   src    = (const int*)d_in[3];
    const int*   dst    = (const int*)d_in[4];
    const float* W_L0   = (const float*)d_in[5];
    const float* W_L1   = (const float*)d_in[6];
    const float* W_enc  = (const float*)d_in[7];
    const float* b_enc  = (const float*)d_in[8];
    const float* W_Y000 = (const float*)d_in[9];
    const float* W_Y110 = (const float*)d_in[10];
    const float* W_Y011 = (const float*)d_in[11];
    const float* W_Y101 = (const float*)d_in[12];
    const float* W_Y111 = (const float*)d_in[13];
    const float* W_m1   = (const float*)d_in[14];
    const float* b_m1   = (const float*)d_in[15];
    const float* W_m2   = (const float*)d_in[16];
    const float* b_m2   = (const float*)d_in[17];
    const float* W_m3   = (const float*)d_in[18];
    float* out = (float*)d_out;

    // zero the poisoned output (atomics accumulate into it)
    cudaMemsetAsync(out, 0, (size_t)out_size * sizeof(float), 0);

    node_kernel<<<(NN + 3) / 4, 128>>>(x_a, x_v, W_L0, W_L1);

    cudaFuncSetAttribute(edge_kernel, cudaFuncAttributeMaxDynamicSharedMemorySize, SMEM_BYTES);
    edge_kernel<<<(EE + 127) / 128, 128, SMEM_BYTES>>>(
        r_ij, src, dst, W_enc, b_enc,
        W_Y000, W_Y110, W_Y011, W_Y101, W_Y111,
        W_m1, b_m1, W_m2, b_m2, W_m3, out);
}

// round 9
// speedup vs baseline: 1.0258x; 1.0258x over previous
#include <cuda_runtime.h>
#include <math.h>

#define NN 50000
#define EE 800000

// Precomputed per-node tables (gathered per edge at dst; L2-resident)
__device__ __align__(16) float g_La[NN * 32];   // [n][c]
__device__ __align__(16) float g_Lv[NN * 96];   // [n][i][c], i in {x,y,z}

// psiA scratch between TP kernel and MLP kernel: packed f32x2 pairs [e][j/2]
__device__ __align__(16) unsigned long long g_psiA2[(size_t)EE * 32];

// ---------------------------------------------------------------------------
// f32x2 helpers (Blackwell packed math; ptxas won't auto-fuse — PTX only)
// ---------------------------------------------------------------------------
__device__ __forceinline__ unsigned long long pk2(float lo, float hi) {
    unsigned long long r;
    asm("mov.b64 %0, {%1, %2};" : "=l"(r) : "f"(lo), "f"(hi));
    return r;
}
__device__ __forceinline__ void upk2(unsigned long long v, float& lo, float& hi) {
    asm("mov.b64 {%0, %1}, %2;" : "=f"(lo), "=f"(hi) : "l"(v));
}
__device__ __forceinline__ unsigned long long ffma2(unsigned long long a,
                                                    unsigned long long b,
                                                    unsigned long long c) {
    unsigned long long d;
    asm("fma.rn.f32x2 %0, %1, %2, %3;" : "=l"(d) : "l"(a), "l"(b), "l"(c));
    return d;
}
// volatile global loads: force re-load (defeat CSE keeping values live across passes)
__device__ __forceinline__ float4 ldg4v(const float4* p) {
    float4 v;
    asm volatile("ld.global.nc.v4.f32 {%0,%1,%2,%3}, [%4];"
                 : "=f"(v.x), "=f"(v.y), "=f"(v.z), "=f"(v.w) : "l"(p));
    return v;
}
__device__ __forceinline__ unsigned long long ldg64v(const unsigned long long* p) {
    unsigned long long v;
    asm volatile("ld.global.nc.b64 %0, [%1];" : "=l"(v) : "l"(p));
    return v;
}

// ============================================================================
// Kernel A: per-node linear maps  La[n][c], Lv[n][i][c]
// ============================================================================
__global__ __launch_bounds__(128) void node_kernel(
    const float* __restrict__ x_a, const float* __restrict__ x_v,
    const float* __restrict__ W_L0, const float* __restrict__ W_L1)
{
    __shared__ float sW0[64 * 32];
    __shared__ float sW1[16 * 32];
    int tid = threadIdx.x;
    for (int i = tid; i < 2048; i += 128) { int c = i >> 6, d = i & 63; sW0[d * 32 + c] = W_L0[i]; }
    for (int i = tid; i < 512;  i += 128) { int c = i >> 4, d = i & 15; sW1[d * 32 + c] = W_L1[i]; }
    __syncthreads();

    int n = blockIdx.x * 4 + (tid >> 5);
    int c = tid & 31;
    if (n >= NN) return;

    const float* xa = x_a + (size_t)n * 64;
    float acc = 0.f;
#pragma unroll
    for (int d = 0; d < 64; d++) acc = fmaf(__ldg(xa + d), sW0[d * 32 + c], acc);
    g_La[(size_t)n * 32 + c] = acc;

    const float* xv = x_v + (size_t)n * 48;
    float ax = 0.f, ay = 0.f, az = 0.f;
#pragma unroll
    for (int d = 0; d < 16; d++) {
        float w = sW1[d * 32 + c];
        ax = fmaf(w, __ldg(xv + d * 3 + 0), ax);
        ay = fmaf(w, __ldg(xv + d * 3 + 1), ay);
        az = fmaf(w, __ldg(xv + d * 3 + 2), az);
    }
    g_Lv[(size_t)n * 96 +  0 + c] = ax;
    g_Lv[(size_t)n * 96 + 32 + c] = ay;
    g_Lv[(size_t)n * 96 + 64 + c] = az;
}

// ============================================================================
// Kernel B: tensor products (two low-register passes) -> scatter psi_v,
//           write psiA (pre-MLP) to scratch.
// ============================================================================
// smem layout (floats)
#define OFF_C    0        // folded radial cos weights  [c][m] 32x16
#define OFF_S    512
#define OFF_W000 1024     // W_Y000^T [c][j] 32x64
#define OFF_W110 3072
#define OFF_W011 5120     // W_Y011^T [c][v] 32x16
#define OFF_W101 5632
#define OFF_W111 6144
#define OFF_BENC 6656
#define TP_SMEM  6688

__global__ __launch_bounds__(128, 4) void edge_tp_kernel(
    const float* __restrict__ r_ij, const int* __restrict__ src, const int* __restrict__ dst,
    const float* __restrict__ W_enc, const float* __restrict__ b_enc,
    const float* __restrict__ W_Y000, const float* __restrict__ W_Y110,
    const float* __restrict__ W_Y011, const float* __restrict__ W_Y101,
    const float* __restrict__ W_Y111, float* __restrict__ out)
{
    __shared__ float sm[TP_SMEM];
    const int tid = threadIdx.x;

    for (int i = tid; i < 512; i += 128) {   // folded radial (16 distinct coeffs)
        int c = i >> 4, m = i & 15;
        sm[OFF_C + i] = W_enc[c * 64 + 2 * m] + W_enc[c * 64 + 2 * m + 1];
        sm[OFF_S + i] = W_enc[c * 64 + 32 + 2 * m] + W_enc[c * 64 + 32 + 2 * m + 1];
    }
    for (int i = tid; i < 2048; i += 128) {
        int c = i >> 6, j = i & 63;
        sm[OFF_W000 + i] = W_Y000[j * 32 + c];
        sm[OFF_W110 + i] = W_Y110[j * 32 + c];
    }
    for (int i = tid; i < 512; i += 128) {
        int c = i >> 4, v = i & 15;
        sm[OFF_W011 + i] = W_Y011[v * 32 + c];
        sm[OFF_W101 + i] = W_Y101[v * 32 + c];
        sm[OFF_W111 + i] = W_Y111[v * 32 + c];
    }
    if (tid < 32) sm[OFF_BENC + tid] = b_enc[tid];
    __syncthreads();

    int e = blockIdx.x * 128 + tid;
    if (e >= EE) return;

    float rx = r_ij[(size_t)e * 3 + 0];
    float ry = r_ij[(size_t)e * 3 + 1];
    float rz = r_ij[(size_t)e * 3 + 2];
    int s = src[e], d = dst[e];

    float dist = sqrtf(rx * rx + ry * ry + rz * rz);

    // ---- Chebyshev radial (multipliers 1..16 of u = pi/5 * dist) ----
    float u = 0.6283185307179586f * dist;
    float c1, s1;
    sincosf(u, &s1, &c1);
    float cosv[16], sinv[16];
    cosv[0] = c1; sinv[0] = s1;
    {
        float cp = 1.f, sp = 0.f, t2 = 2.f * c1;
#pragma unroll
        for (int m = 1; m < 16; m++) {
            float cn = fmaf(t2, cosv[m - 1], -cp);
            float sn = fmaf(t2, sinv[m - 1], -sp);
            cp = cosv[m - 1]; sp = sinv[m - 1];
            cosv[m] = cn; sinv[m] = sn;
        }
    }

    // ---- phi_a ----
    float phi[32];
    {
        const float4* sC4 = (const float4*)(sm + OFF_C);
        const float4* sS4 = (const float4*)(sm + OFF_S);
#pragma unroll
        for (int c = 0; c < 32; c++) {
            float acc = sm[OFF_BENC + c];
#pragma unroll
            for (int m4 = 0; m4 < 4; m4++) {
                float4 wc = sC4[c * 4 + m4];
                float4 ws = sS4[c * 4 + m4];
                acc = fmaf(wc.x, cosv[m4 * 4 + 0], acc);
                acc = fmaf(wc.y, cosv[m4 * 4 + 1], acc);
                acc = fmaf(wc.z, cosv[m4 * 4 + 2], acc);
                acc = fmaf(wc.w, cosv[m4 * 4 + 3], acc);
                acc = fmaf(ws.x, sinv[m4 * 4 + 0], acc);
                acc = fmaf(ws.y, sinv[m4 * 4 + 1], acc);
                acc = fmaf(ws.z, sinv[m4 * 4 + 2], acc);
                acc = fmaf(ws.w, sinv[m4 * 4 + 3], acc);
            }
            phi[c] = acc;
        }
    }

    // ---- squashed edge vector rh ----
    float nrm = 1.4f * dist;
    float scl = 1.4f * tanhf(nrm) / fmaxf(nrm, 1e-12f);
    float rh0 = rx * scl, rh1 = ry * scl, rh2 = rz * scl;

    const float4* La4 = (const float4*)(g_La + (size_t)d * 32);
    const float4* Lv4 = (const float4*)(g_Lv + (size_t)d * 96);

    // =========================== PASS A: psi_v ===========================
    {
        unsigned long long a2[8], px2[8], py2[8], pz2[8];
#pragma unroll
        for (int i = 0; i < 8; i++) { a2[i] = 0; px2[i] = 0; py2[i] = 0; pz2[i] = 0; }

#pragma unroll
        for (int q = 0; q < 8; q++) {
            float4 la4 = ldg4v(La4 + q);
            float4 lx4 = ldg4v(Lv4 + q);
            float4 ly4 = ldg4v(Lv4 + 8 + q);
            float4 lz4 = ldg4v(Lv4 + 16 + q);
            float laA[4] = {la4.x, la4.y, la4.z, la4.w};
            float lxA[4] = {lx4.x, lx4.y, lx4.z, lx4.w};
            float lyA[4] = {ly4.x, ly4.y, ly4.z, ly4.w};
            float lzA[4] = {lz4.x, lz4.y, lz4.z, lz4.w};
#pragma unroll
            for (int k = 0; k < 4; k++) {
                const int c = q * 4 + k;
                const float p = phi[c];
                const float y000 = laA[k] * p;
                const float plx = p * lxA[k], ply = p * lyA[k], plz = p * lzA[k];
                const float crx = fmaf(ply, rh2, -plz * rh1);
                const float cry = fmaf(plz, rh0, -plx * rh2);
                const float crz = fmaf(plx, rh1, -ply * rh0);
                const unsigned long long by  = pk2(y000, y000);
                const unsigned long long bx  = pk2(plx, plx);
                const unsigned long long bby = pk2(ply, ply);
                const unsigned long long bz  = pk2(plz, plz);
                const unsigned long long bcx = pk2(crx, crx);
                const unsigned long long bcy = pk2(cry, cry);
                const unsigned long long bcz = pk2(crz, crz);
                const ulonglong2* wA = (const ulonglong2*)(sm + OFF_W011 + c * 16);
                const ulonglong2* wB = (const ulonglong2*)(sm + OFF_W101 + c * 16);
                const ulonglong2* wC = (const ulonglong2*)(sm + OFF_W111 + c * 16);
#pragma unroll
                for (int v4 = 0; v4 < 4; v4++) {
                    ulonglong2 a = wA[v4], b = wB[v4], w = wC[v4];
                    a2[2 * v4 + 0] = ffma2(a.x, by, a2[2 * v4 + 0]);
                    a2[2 * v4 + 1] = ffma2(a.y, by, a2[2 * v4 + 1]);
                    px2[2 * v4 + 0] = ffma2(b.x, bx, ffma2(w.x, bcx, px2[2 * v4 + 0]));
                    px2[2 * v4 + 1] = ffma2(b.y, bx, ffma2(w.y, bcx, px2[2 * v4 + 1]));
                    py2[2 * v4 + 0] = ffma2(b.x, bby, ffma2(w.x, bcy, py2[2 * v4 + 0]));
                    py2[2 * v4 + 1] = ffma2(b.y, bby, ffma2(w.y, bcy, py2[2 * v4 + 1]));
                    pz2[2 * v4 + 0] = ffma2(b.x, bz, ffma2(w.x, bcz, pz2[2 * v4 + 0]));
                    pz2[2 * v4 + 1] = ffma2(b.y, bz, ffma2(w.y, bcz, pz2[2 * v4 + 1]));
                }
            }
        }
        // scatter psi_v
        float* outV = out + (size_t)NN * 64 + (size_t)s * 48;
#pragma unroll
        for (int v2 = 0; v2 < 8; v2++) {
            float aL, aH, xL, xH, yL, yH, zL, zH;
            upk2(a2[v2], aL, aH);
            upk2(px2[v2], xL, xH);
            upk2(py2[v2], yL, yH);
            upk2(pz2[v2], zL, zH);
            int v = 2 * v2;
            atomicAdd(outV + 3 * v + 0, 0.1f * fmaf(aL, rh0, xL));
            atomicAdd(outV + 3 * v + 1, 0.1f * fmaf(aL, rh1, yL));
            atomicAdd(outV + 3 * v + 2, 0.1f * fmaf(aL, rh2, zL));
            atomicAdd(outV + 3 * v + 3, 0.1f * fmaf(aH, rh0, xH));
            atomicAdd(outV + 3 * v + 4, 0.1f * fmaf(aH, rh1, yH));
            atomicAdd(outV + 3 * v + 5, 0.1f * fmaf(aH, rh2, zH));
        }
    }

    // =========================== PASS B: psiA ===========================
    {
        unsigned long long pj[32];
#pragma unroll
        for (int i = 0; i < 32; i++) pj[i] = 0;

#pragma unroll
        for (int q = 0; q < 8; q++) {
            float4 la4 = ldg4v(La4 + q);
            float4 lx4 = ldg4v(Lv4 + q);
            float4 ly4 = ldg4v(Lv4 + 8 + q);
            float4 lz4 = ldg4v(Lv4 + 16 + q);
            float laA[4] = {la4.x, la4.y, la4.z, la4.w};
            float lxA[4] = {lx4.x, lx4.y, lx4.z, lx4.w};
            float lyA[4] = {ly4.x, ly4.y, ly4.z, ly4.w};
            float lzA[4] = {lz4.x, lz4.y, lz4.z, lz4.w};
#pragma unroll
            for (int k = 0; k < 4; k++) {
                const int c = q * 4 + k;
                const float p = phi[c];
                const float y000 = laA[k] * p;
                const float y110 = p * fmaf(lxA[k], rh0, fmaf(lyA[k], rh1, lzA[k] * rh2));
                const unsigned long long b0 = pk2(y000, y000);
                const unsigned long long b1 = pk2(y110, y110);
                const ulonglong2* w0 = (const ulonglong2*)(sm + OFF_W000 + c * 64);
                const ulonglong2* w1 = (const ulonglong2*)(sm + OFF_W110 + c * 64);
#pragma unroll
                for (int j4 = 0; j4 < 16; j4++) {
                    ulonglong2 a = w0[j4], b = w1[j4];
                    pj[2 * j4 + 0] = ffma2(a.x, b0, ffma2(b.x, b1, pj[2 * j4 + 0]));
                    pj[2 * j4 + 1] = ffma2(a.y, b0, ffma2(b.y, b1, pj[2 * j4 + 1]));
                }
            }
        }
        // store to scratch (128-bit stores)
        ulonglong2* gp = (ulonglong2*)(g_psiA2 + (size_t)e * 32);
#pragma unroll
        for (int i = 0; i < 16; i++) {
            ulonglong2 t; t.x = pj[2 * i]; t.y = pj[2 * i + 1];
            gp[i] = t;
        }
    }
}

// ============================================================================
// Kernel C: residual MLP on psiA (packed f32x2), scatter psi_a
// ============================================================================
#define MOFF_M1 0
#define MOFF_M2 4096
#define MOFF_M3 8192
#define MOFF_B1 12288
#define MOFF_B2 12352
#define M_SMEM_FLOATS 12416
#define M_SMEM_BYTES  (M_SMEM_FLOATS * 4)

__device__ __forceinline__ void layer_packed(const float* __restrict__ sw,
                                             const float* __restrict__ sb,
                                             const unsigned long long (&x)[32],
                                             unsigned long long (&h)[32])
{
#pragma unroll
    for (int j2 = 0; j2 < 32; j2++) {
        unsigned long long accA = 0, accB = 0;
        const ulonglong2* rA = (const ulonglong2*)(sw + (2 * j2 + 0) * 64);
        const ulonglong2* rB = (const ulonglong2*)(sw + (2 * j2 + 1) * 64);
#pragma unroll
        for (int k4 = 0; k4 < 16; k4++) {
            ulonglong2 wa = rA[k4], wb = rB[k4];
            accA = ffma2(wa.x, x[2 * k4 + 0], accA);
            accA = ffma2(wa.y, x[2 * k4 + 1], accA);
            accB = ffma2(wb.x, x[2 * k4 + 0], accB);
            accB = ffma2(wb.y, x[2 * k4 + 1], accB);
        }
        float aL, aH, bL, bH;
        upk2(accA, aL, aH); upk2(accB, bL, bH);
        float a = aL + aH + sb[2 * j2 + 0];
        float b = bL + bH + sb[2 * j2 + 1];
        a = fmaxf(a, 0.1f * a);
        b = fmaxf(b, 0.1f * b);
        h[j2] = pk2(a, b);
    }
}

__global__ __launch_bounds__(128, 3) void edge_mlp_kernel(
    const float* __restrict__ W_m1, const float* __restrict__ b_m1,
    const float* __restrict__ W_m2, const float* __restrict__ b_m2,
    const float* __restrict__ W_m3, const int* __restrict__ src,
    float* __restrict__ out)
{
    extern __shared__ float sm[];
    const int tid = threadIdx.x;
    for (int i = tid; i < 4096; i += 128) {
        sm[MOFF_M1 + i] = W_m1[i];
        sm[MOFF_M2 + i] = W_m2[i];
        sm[MOFF_M3 + i] = W_m3[i];
    }
    if (tid < 64) { sm[MOFF_B1 + tid] = b_m1[tid]; sm[MOFF_B2 + tid] = b_m2[tid]; }
    __syncthreads();

    int e = blockIdx.x * 128 + tid;
    if (e >= EE) return;
    int s = src[e];

    unsigned long long xp[32], hq[32];
    {
        const ulonglong2* gx = (const ulonglong2*)(g_psiA2 + (size_t)e * 32);
#pragma unroll
        for (int i = 0; i < 16; i++) {
            ulonglong2 t = gx[i];
            xp[2 * i] = t.x; xp[2 * i + 1] = t.y;
        }
    }
    layer_packed(sm + MOFF_M1, sm + MOFF_B1, xp, hq);   // h1 = lrelu(W1 x + b1)
    layer_packed(sm + MOFF_M2, sm + MOFF_B2, hq, xp);   // h2 = lrelu(W2 h1 + b2)  (xp reused)

    // layer3 (no bias/act) + residual (reload x from scratch; volatile defeats CSE)
    float* outA = out + (size_t)s * 64;
#pragma unroll
    for (int j2 = 0; j2 < 32; j2++) {
        unsigned long long accA = 0, accB = 0;
        const ulonglong2* rA = (const ulonglong2*)(sm + MOFF_M3 + (2 * j2 + 0) * 64);
        const ulonglong2* rB = (const ulonglong2*)(sm + MOFF_M3 + (2 * j2 + 1) * 64);
#pragma unroll
        for (int k4 = 0; k4 < 16; k4++) {
            ulonglong2 wa = rA[k4], wb = rB[k4];
            accA = ffma2(wa.x, xp[2 * k4 + 0], accA);
            accA = ffma2(wa.y, xp[2 * k4 + 1], accA);
            accB = ffma2(wb.x, xp[2 * k4 + 0], accB);
            accB = ffma2(wb.y, xp[2 * k4 + 1], accB);
        }
        float aL, aH, bL, bH;
        upk2(accA, aL, aH); upk2(accB, bL, bH);
        unsigned long long xq = ldg64v(g_psiA2 + (size_t)e * 32 + j2);
        float xA, xB; upk2(xq, xA, xB);
        atomicAdd(outA + 2 * j2 + 0, 0.1f * (aL + aH + xA));
        atomicAdd(outA + 2 * j2 + 1, 0.1f * (bL + bH + xB));
    }
}

// ============================================================================
// launcher
// ============================================================================
extern "C" void kernel_launch(void* const* d_in, const int* in_sizes, int n_in,
                              void* d_out, int out_size)
{
    const float* r_ij   = (const float*)d_in[0];
    const float* x_a    = (const float*)d_in[1];
    const float* x_v    = (const float*)d_in[2];
    const int*   src    = (const int*)d_in[3];
    const int*   dst    = (const int*)d_in[4];
    const float* W_L0   = (const float*)d_in[5];
    const float* W_L1   = (const float*)d_in[6];
    const float* W_enc  = (const float*)d_in[7];
    const float* b_enc  = (const float*)d_in[8];
    const float* W_Y000 = (const float*)d_in[9];
    const float* W_Y110 = (const float*)d_in[10];
    const float* W_Y011 = (const float*)d_in[11];
    const float* W_Y101 = (const float*)d_in[12];
    const float* W_Y111 = (const float*)d_in[13];
    const float* W_m1   = (const float*)d_in[14];
    const float* b_m1   = (const float*)d_in[15];
    const float* W_m2   = (const float*)d_in[16];
    const float* b_m2   = (const float*)d_in[17];
    const float* W_m3   = (const float*)d_in[18];
    float* out = (float*)d_out;

    cudaMemsetAsync(out, 0, (size_t)out_size * sizeof(float), 0);

    node_kernel<<<(NN + 3) / 4, 128>>>(x_a, x_v, W_L0, W_L1);

    edge_tp_kernel<<<EE / 128, 128>>>(
        r_ij, src, dst, W_enc, b_enc,
        W_Y000, W_Y110, W_Y011, W_Y101, W_Y111, out);

    cudaFuncSetAttribute(edge_mlp_kernel, cudaFuncAttributeMaxDynamicSharedMemorySize, M_SMEM_BYTES);
    edge_mlp_kernel<<<EE / 128, 128, M_SMEM_BYTES>>>(
        W_m1, b_m1, W_m2, b_m2, W_m3, src, out);
}